// round 17
// baseline (speedup 1.0000x reference)
#include <cuda_runtime.h>
#include <math_constants.h>
#include <cstdint>

// SPP: out = concat(x, pool5(x), pool9(x), pool13(x)) along channels.
// Cascade identity: pool9 = pool5(pool5(x)), pool13 = pool5(pool9(x)),
// each pool5 separable (horizontal then vertical 5-max).
//
// Base = R10 (confirmed local optimum: 54.3us bench / 50.4us ncu, DRAM 69%):
// block = 8 contiguous planes, 4 warps; warp = 2 planes, width-16 shuffles,
// pair-max horizontal 5-max, register-ring vertical 5-max, in-place cascade;
// staging STS fused into compute; 32 KB evict-first bulk stores; 2x32 KB ring.
//
// R16 change: section 0 (pure pass-through) becomes an all-async DMA chain:
//   cp.async.bulk GLOBAL->SMEM (mbarrier) -> cp.async.bulk SMEM->GLOBAL.
// It never touches registers/STS, and its drain is issued during the LDG
// front (thread 0 waits the mbarrier while other lanes load). Removes the
// sec0 staging loop + fence + barrier from every CTA's startup path.
// Ring: sec0=buf1(DMA), sec1=buf0, sec2=buf1, sec3=buf0.
//
// x: (32, 512, 32, 32) f32 -> out: (32, 2048, 32, 32) f32.

#define NCHAN 512
#define HW 1024
#define PLANES (32 * 512)
#define WARPS_PER_BLK 4
#define PLANES_PER_BLK (WARPS_PER_BLK * 2)
#define SEC_FLOATS (PLANES_PER_BLK * HW)          // 8192 floats
#define SEC_BYTES  (SEC_FLOATS * 4)               // 32768 bytes
#define SMEM_BYTES (2 * SEC_BYTES)                // 64 KB dynamic

__device__ __forceinline__ uint32_t smem_u32(const void* p) {
    uint32_t a;
    asm("{ .reg .u64 t; cvta.to.shared.u64 t, %1; cvt.u32.u64 %0, t; }"
        : "=r"(a) : "l"(p));
    return a;
}

__device__ __forceinline__ void bulk_store_ef(const float* dst, uint32_t s) {
    asm volatile(
        "{\n\t"
        ".reg .b64 pol;\n\t"
        "createpolicy.fractional.L2::evict_first.b64 pol, 1.0;\n\t"
        "cp.async.bulk.global.shared::cta.bulk_group.L2::cache_hint "
        "[%0], [%1], %2, pol;\n\t"
        "}"
        :: "l"(dst), "r"(s), "n"(SEC_BYTES) : "memory");
    asm volatile("cp.async.bulk.commit_group;" ::: "memory");
}

__global__ __launch_bounds__(32 * WARPS_PER_BLK)
void spp_kernel(const float* __restrict__ x, float* __restrict__ out) {
    extern __shared__ float sbuf[];               // [2][SEC_FLOATS]
    __shared__ uint64_t mbar;                     // DMA-load completion

    const int lane = threadIdx.x & 31;
    const int wid  = threadIdx.x >> 5;
    const int sub  = lane >> 4;                   // plane within warp (0/1)
    const int l    = lane & 15;                   // column-pair index

    const int pl_local = wid * 2 + sub;           // 0..7 within block
    const int plane0 = blockIdx.x * PLANES_PER_BLK;
    const int plane  = plane0 + pl_local;         // n*512 + c
    const int n  = plane0 >> 9;
    const int c0 = plane0 & (NCHAN - 1);

    const float2* __restrict__ xin =
        (const float2*)(x + (size_t)plane * HW) + l;
    const float* __restrict__ ob =
        out + ((size_t)n * (4 * NCHAN) + c0) * HW;
    const float* __restrict__ xsec = x + (size_t)plane0 * HW;  // 32 KB tile

    float2* stg0 = (float2*)(sbuf)              + pl_local * (HW / 2) + l;
    float2* stg1 = (float2*)(sbuf + SEC_FLOATS) + pl_local * (HW / 2) + l;
    const uint32_t s0 = smem_u32(sbuf);
    const uint32_t s1 = smem_u32(sbuf + SEC_FLOATS);
    const uint32_t mb = smem_u32(&mbar);

    // ---- sec0 DMA: GLOBAL -> buf1, tracked by mbarrier (thread 0 only) ----
    if (threadIdx.x == 0) {
        asm volatile("mbarrier.init.shared.b64 [%0], 1;" :: "r"(mb) : "memory");
        asm volatile("fence.proxy.async.shared::cta;" ::: "memory");
        asm volatile("mbarrier.arrive.expect_tx.shared.b64 _, [%0], %1;"
                     :: "r"(mb), "r"((uint32_t)SEC_BYTES) : "memory");
        asm volatile(
            "cp.async.bulk.shared::cta.global.mbarrier::complete_tx::bytes "
            "[%0], [%1], %2, [%3];"
            :: "r"(s1), "l"(xsec), "n"(SEC_BYTES), "r"(mb) : "memory");
    }

    // ---- LDG front: lane's 2-column strip into registers (all threads;
    //      overlaps the DMA load) ----
    float2 v[32];
    #pragma unroll
    for (int y = 0; y < 32; ++y) v[y] = xin[y * 16];

    // ---- thread 0: wait DMA, then launch sec0 store (G0) from buf1.
    //      Lanes 1-31 of warp 0 proceed; reconverge at pool-1's shuffles. ----
    if (threadIdx.x == 0) {
        uint32_t done;
        asm volatile(
            "{\n\t"
            ".reg .pred p;\n\t"
            "WAIT_%=:\n\t"
            "mbarrier.try_wait.parity.shared.b64 p, [%1], 0, 0x989680;\n\t"
            "selp.b32 %0, 1, 0, p;\n\t"
            "@!p bra.uni WAIT_%=;\n\t"
            "}"
            : "=r"(done) : "r"(mb) : "memory");
        bulk_store_ef(ob, s1);                    // G0 = sec0
    }

    const unsigned FULL = 0xffffffffu;
    const float NEG = -CUDART_INF_F;

    #pragma unroll
    for (int p = 0; p < 3; ++p) {
        // Staging ring: pool0->buf0, pool1->buf1, pool2->buf0.
        // p=0: buf0 untouched, no wait/barrier needed (threads only write
        //      their own slots).
        // p=1: buf1 was read by G0 (sec0), issued one full compute phase
        //      ago: retire it (keep newest group in flight).
        // p=2: buf0 was read by G1 (sec1): retire it likewise.
        const int b = p & 1;                      // 0,1,0
        if (p >= 1) {
            if (threadIdx.x == 0)
                asm volatile("cp.async.bulk.wait_group.read 1;" ::: "memory");
            __syncthreads();
        }

        float2* stg = b ? stg1 : stg0;

        // ---- compute pool p; staging stores fused into the loop ----
        float2 r0 = {NEG, NEG}, r1 = {NEG, NEG},
               r2 = {NEG, NEG}, r3 = {NEG, NEG};

        #pragma unroll
        for (int y = 0; y < 34; ++y) {
            float2 h;
            if (y < 32) {
                const float a = v[y].x, bb = v[y].y;
                const float pm = fmaxf(a, bb);
                const float lp = __shfl_up_sync  (FULL, pm, 1, 16);
                const float lb = __shfl_up_sync  (FULL, bb, 1, 16);
                const float ra = __shfl_down_sync(FULL, a,  1, 16);
                const float rp = __shfl_down_sync(FULL, pm, 1, 16);
                h.x = fmaxf(fmaxf(lp, pm), ra);   // cols 2l-2 .. 2l+2
                h.y = fmaxf(fmaxf(lb, pm), rp);   // cols 2l-1 .. 2l+3
            } else {
                h.x = NEG; h.y = NEG;             // bottom padding rows
            }
            if (y >= 2) {
                float2 m;
                m.x = fmaxf(fmaxf(fmaxf(r0.x, r1.x), fmaxf(r2.x, r3.x)), h.x);
                m.y = fmaxf(fmaxf(fmaxf(r0.y, r1.y), fmaxf(r2.y, r3.y)), h.y);
                v[y - 2] = m;                     // in-place: feeds next pool
                stg[(y - 2) * 16] = m;            // fused staging STS
            }
            r0 = r1; r1 = r2; r2 = r3; r3 = h;
        }

        // ---- publish + bulk store section p+1 (G1,G2,G3) ----
        asm volatile("fence.proxy.async.shared::cta;" ::: "memory");
        __syncthreads();
        if (threadIdx.x == 0)
            bulk_store_ef(ob + (size_t)(p + 1) * NCHAN * HW, b ? s1 : s0);
    }

    // SMEM must outlive all pending bulk reads.
    if (threadIdx.x == 0)
        asm volatile("cp.async.bulk.wait_group.read 0;" ::: "memory");
    __syncthreads();
}

extern "C" void kernel_launch(void* const* d_in, const int* in_sizes, int n_in,
                              void* d_out, int out_size) {
    const float* x = (const float*)d_in[0];
    float* out     = (float*)d_out;
    cudaFuncSetAttribute(spp_kernel,
                         cudaFuncAttributeMaxDynamicSharedMemorySize, SMEM_BYTES);
    spp_kernel<<<PLANES / PLANES_PER_BLK, 32 * WARPS_PER_BLK, SMEM_BYTES>>>(x, out);
}